// round 14
// baseline (speedup 1.0000x reference)
#include <cuda_runtime.h>
#include <cstdint>
#include <math.h>

#define BB_L 200
#define BB_D 128
#define BB_H 100
#define NT 1024

// ---- SMEM layout (float indices) ----
#define OFF_XA  0                     // x tf32 pairs [208][136]        -> 28288 f
#define OFF_WBP 28288                 // B pairs uint4[16*7*32]         -> 14336 f
#define OFF_WBO (OFF_WBP + 14336)     // B odd frags float2[16*2*32]    ->  2048 f
#define OFF_CV  (OFF_WBO + 2048)      // (cj, vv) float2[128]           ->   256 f
#define OFF_QS  (OFF_CV + 256)        // 128 f
#define OFF_SC  (OFF_QS + 128)        // 208 f
#define OFF_MK  (OFF_SC + 208)        // 208 f
#define OFF_SCP (OFF_MK + 208)        // partial scores [208][2] -> 416 f
#define OFF_RED (OFF_SCP + 416)       // 16 f
#define SMEM_FLOATS (OFF_RED + 16)
#define SMEM_BYTES (SMEM_FLOATS * 4)

// B pairs: u4 idx = (ks*7 + p)*32 + lane ; pair p covers nt(2p), nt(2p+1)
// value = (w[d0][j0], w[d1][j0], w[d0][j1], w[d1][j1]), d0=8ks+t, d1=d0+4, j=8nt+g
__device__ uint4 g_wkp[3584];
// odd frags: idx = (ks*2 + half)*32 + lane ; half0 -> nt6, half1 -> nt12
__device__ float2 g_wko[1024];

__device__ __forceinline__ uint32_t to_tf32(float f) {
    uint32_t r;
    asm("cvt.rna.tf32.f32 %0, %1;" : "=r"(r) : "f"(f));
    return r;
}
__device__ __forceinline__ float tanh_fast(float x) {
    float y;
    asm("tanh.approx.f32 %0, %1;" : "=f"(y) : "f"(x));
    return y;
}
__device__ __forceinline__ void mma_tf32(float* c,
                                         uint32_t a0, uint32_t a1, uint32_t a2, uint32_t a3,
                                         uint32_t b0, uint32_t b1) {
    asm volatile(
        "mma.sync.aligned.m16n8k8.row.col.f32.tf32.tf32.f32 "
        "{%0,%1,%2,%3}, {%4,%5,%6,%7}, {%8,%9}, {%0,%1,%2,%3};"
        : "+f"(c[0]), "+f"(c[1]), "+f"(c[2]), "+f"(c[3])
        : "r"(a0), "r"(a1), "r"(a2), "r"(a3), "r"(b0), "r"(b1));
}

// ---------------- prep: pack Wk fragments (tf32) ----------------
__global__ void pack_wk_kernel(const float* __restrict__ Wk) {
    int i = blockIdx.x * 256 + threadIdx.x;
    if (i < 3584) {
        int lane = i & 31;
        int t = lane & 3;
        int g = lane >> 2;
        int kp = i >> 5;
        int p = kp % 7;
        int ks = kp / 7;
        int j0 = 8 * (2 * p) + g;
        int j1 = 8 * (2 * p + 1) + g;
        int d0 = 8 * ks + t, d1 = d0 + 4;
        uint4 o;
        o.x = (j0 < BB_H) ? to_tf32(Wk[d0 * BB_H + j0]) : 0u;
        o.y = (j0 < BB_H) ? to_tf32(Wk[d1 * BB_H + j0]) : 0u;
        o.z = (j1 < BB_H) ? to_tf32(Wk[d0 * BB_H + j1]) : 0u;
        o.w = (j1 < BB_H) ? to_tf32(Wk[d1 * BB_H + j1]) : 0u;
        g_wkp[i] = o;
    }
    if (i < 1024) {
        int lane = i & 31;
        int t = lane & 3;
        int g = lane >> 2;
        int kh = i >> 5;
        int half = kh & 1;
        int ks = kh >> 1;
        int j = half ? (96 + g) : (48 + g);   // nt12 : nt6
        int d0 = 8 * ks + t, d1 = d0 + 4;
        float2 o;
        o.x = (j < BB_H) ? __uint_as_float(to_tf32(Wk[d0 * BB_H + j])) : 0.f;
        o.y = (j < BB_H) ? __uint_as_float(to_tf32(Wk[d1 * BB_H + j])) : 0.f;
        g_wko[i] = o;
    }
}

__global__ void __launch_bounds__(NT, 1)
mxqa_mma_kernel(const float* __restrict__ x, const float* __restrict__ q,
                const float* __restrict__ bk,
                const float* __restrict__ Wq, const float* __restrict__ v,
                float* __restrict__ out)
{
    extern __shared__ float sm[];
    float* xa = sm + OFF_XA;
    float2* xa2 = reinterpret_cast<float2*>(sm + OFF_XA);
    float4* xa4 = reinterpret_cast<float4*>(sm + OFF_XA);
    float2* cvv = reinterpret_cast<float2*>(sm + OFF_CV);
    float* qs = sm + OFF_QS;
    float* sc = sm + OFF_SC;
    float* mk = sm + OFF_MK;
    float* scp = sm + OFF_SCP;
    float* red = sm + OFF_RED;

    const int tid = threadIdx.x;
    const int lane = tid & 31;
    const int warp = tid >> 5;
    const int b = blockIdx.x;
    const int g = lane >> 2;     // fragment row group 0..7
    const int t = lane & 3;      // k/col slot 0..3

    // ---------------- Phase 1a: zero-inits (finish BEFORE mask writes) ----------
    if (tid < 128) qs[tid] = q[(long long)b * 128 + tid];
    if (tid < 208) { sc[tid] = 0.f; mk[tid] = 0.f; }
    for (int i = tid; i < 8 * 136; i += NT) xa[200 * 136 + i] = 0.f;  // pad rows 200..207
    __syncthreads();   // ORDER: mk zero-init before mk[l]=1 writes below

    // ---------------- Phase 1b: staging ----------------
    // B pairs + odd frags: straight copies
    {
        const uint4* src = g_wkp;
        uint4* dst = reinterpret_cast<uint4*>(sm + OFF_WBP);
        for (int i = tid; i < 3584; i += NT) dst[i] = src[i];
        const uint4* srco = reinterpret_cast<const uint4*>(g_wko);
        uint4* dsto = reinterpret_cast<uint4*>(sm + OFF_WBO);
        if (tid < 512) dsto[tid] = srco[tid];
    }

    // x -> tf32 pairs (x[8k+t], x[8k+t+4]); mask from original fp32
    {
        const float4* xb4 = reinterpret_cast<const float4*>(x + (long long)b * (BB_L * BB_D));
        for (int u = tid; u < BB_L * 16; u += NT) {
            int l = u >> 4;
            int ks = u & 15;
            float4 f0 = xb4[2 * u];
            float4 f1 = xb4[2 * u + 1];
            uint4 o0, o1;   // pairs (x[8k+t], x[8k+t+4]) as tf32 bit patterns
            o0.x = to_tf32(f0.x); o0.y = to_tf32(f1.x);
            o0.z = to_tf32(f0.y); o0.w = to_tf32(f1.y);
            o1.x = to_tf32(f0.z); o1.y = to_tf32(f1.z);
            o1.z = to_tf32(f0.w); o1.w = to_tf32(f1.w);
            reinterpret_cast<uint4*>(xa4)[l * 34 + 2 * ks] = o0;
            reinterpret_cast<uint4*>(xa4)[l * 34 + 2 * ks + 1] = o1;
            if (f0.x != 0.f || f0.y != 0.f || f0.z != 0.f || f0.w != 0.f ||
                f1.x != 0.f || f1.y != 0.f || f1.z != 0.f || f1.w != 0.f)
                mk[l] = 1.f;
        }
    }
    __syncthreads();

    // ---------------- Phase 2: GEMM (warps 0-25) || cj (warps 26-31) ----------------
    // warp = 2*mt + half; mt 0..12 rows [16mt,16mt+16); half0: nt0-6, half1: nt6-12
    float acc[7][4];
    const int mt = warp >> 1;
    const int half = warp & 1;
    if (warp < 26) {
        const int m0 = mt * 16;
        const float2* pa0 = xa2 + (m0 + g) * 68 + t;   // tf32 bits in float2
        const float2* pa1 = pa0 + 8 * 68;
        const uint4* pb4 = reinterpret_cast<const uint4*>(sm + OFF_WBP) + half * 3 * 32 + lane;
        const float2* pbo = reinterpret_cast<const float2*>(sm + OFF_WBO) + half * 32 + lane;
#pragma unroll
        for (int nt = 0; nt < 7; ++nt)
#pragma unroll
            for (int k = 0; k < 4; ++k) acc[nt][k] = 0.f;

#pragma unroll
        for (int ks = 0; ks < 16; ++ks) {
            float2 p0 = pa0[4 * ks];
            float2 p1 = pa1[4 * ks];
            uint32_t a0 = __float_as_uint(p0.x);
            uint32_t a1 = __float_as_uint(p1.x);
            uint32_t a2 = __float_as_uint(p0.y);
            uint32_t a3 = __float_as_uint(p1.y);
            uint4 B0 = pb4[ks * 224];
            uint4 B1 = pb4[ks * 224 + 32];
            uint4 B2 = pb4[ks * 224 + 64];
            float2 bo = pbo[ks * 64];
            mma_tf32(acc[0], a0, a1, a2, a3, B0.x, B0.y);
            mma_tf32(acc[1], a0, a1, a2, a3, B0.z, B0.w);
            mma_tf32(acc[2], a0, a1, a2, a3, B1.x, B1.y);
            mma_tf32(acc[3], a0, a1, a2, a3, B1.z, B1.w);
            mma_tf32(acc[4], a0, a1, a2, a3, B2.x, B2.y);
            mma_tf32(acc[5], a0, a1, a2, a3, B2.z, B2.w);
            mma_tf32(acc[6], a0, a1, a2, a3,
                     __float_as_uint(bo.x), __float_as_uint(bo.y));
        }
    } else {
        // cj[j] = bk[j] + sum_d q[d]*Wq[d][j]; vv[j] = v[j] (pad to 104)
        const int j = tid - 26 * 32;   // 0..191, only j<104 active
        if (j < 104) {
            float s = 0.f, vw = 0.f;
            if (j < BB_H) {
                s = bk[j];
#pragma unroll 8
                for (int d = 0; d < 128; ++d) s += qs[d] * Wq[d * BB_H + j];
                vw = v[j];
            }
            cvv[j] = make_float2(s, vw);
        }
    }
    __syncthreads();

    // ---------------- Phase 3: epilogue on fragments (warps 0-25) ----------------
    // half0: acc n -> nt n (0..6); half1: acc n -> nt 6+n (6..12); skip half1 acc0 (nt6 dup)
    if (warp < 26) {
        float s0 = 0.f, s1 = 0.f;
#pragma unroll
        for (int nt = 0; nt < 7; ++nt) {
            if (half && nt == 0) continue;
            int j0 = half * 48 + nt * 8 + 2 * t;
            float2 c0 = cvv[j0];
            float2 c1 = cvv[j0 + 1];
            s0 += tanh_fast(acc[nt][0] + c0.x) * c0.y;
            s0 += tanh_fast(acc[nt][1] + c1.x) * c1.y;
            s1 += tanh_fast(acc[nt][2] + c0.x) * c0.y;
            s1 += tanh_fast(acc[nt][3] + c1.x) * c1.y;
        }
        s0 += __shfl_xor_sync(0xffffffffu, s0, 1);
        s0 += __shfl_xor_sync(0xffffffffu, s0, 2);
        s1 += __shfl_xor_sync(0xffffffffu, s1, 1);
        s1 += __shfl_xor_sync(0xffffffffu, s1, 2);
        if (t == 0) {
            int l0 = mt * 16 + g;
            scp[2 * l0 + half] = s0;
            scp[2 * (l0 + 8) + half] = s1;
        }
    }
    __syncthreads();

    // ---------------- Phase 4: combine halves, exp, normalize ----------------
    {
        float a = 0.f;
        if (tid < 208) {
            a = expf(scp[2 * tid] + scp[2 * tid + 1]) * mk[tid];
            sc[tid] = a;
        }
        if (warp < 7) {
#pragma unroll
            for (int o = 16; o; o >>= 1) a += __shfl_xor_sync(0xffffffffu, a, o);
            if (lane == 0) red[warp] = a;
        }
    }
    __syncthreads();
    if (tid == 0) {
        float tsum = 0.f;
#pragma unroll
        for (int w = 0; w < 7; ++w) tsum += red[w];
        red[0] = 1.f / (tsum + 1e-7f);
    }
    __syncthreads();
    const float winv = red[0];

    // ---------------- Phase 5: out[b][d] = winv * sum_l sc[l] * x_tf32[l][d] ----------------
    {
        const int d = tid & 127;
        const int oct = tid >> 7;            // 0..7
        const int r = d & 7;
        const int off = 8 * (d >> 3) + 2 * (r & 3) + (r >> 2);
        float a = 0.f;
        const int l0 = oct * 25;
#pragma unroll 5
        for (int l = l0; l < l0 + 25; ++l)
            a += sc[l] * xa[l * 136 + off];   // tf32-rounded x (valid fp32 values)
        sm[OFF_WBP + tid] = a;                // reuse B region (GEMM done)
    }
    __syncthreads();
    if (tid < 128) {
        float o = 0.f;
#pragma unroll
        for (int k = 0; k < 8; ++k) o += sm[OFF_WBP + tid + 128 * k];
        out[(long long)b * 128 + tid] = o * winv;
    }
}

extern "C" void kernel_launch(void* const* d_in, const int* in_sizes, int n_in,
                              void* d_out, int out_size)
{
    const float* x  = (const float*)d_in[0];
    const float* q  = (const float*)d_in[1];
    const float* Wk = (const float*)d_in[2];
    const float* bk = (const float*)d_in[3];
    const float* Wq = (const float*)d_in[4];
    const float* v  = (const float*)d_in[5];
    float* out = (float*)d_out;

    const int B = in_sizes[1] / BB_D;  // q is [B, 128]

    pack_wk_kernel<<<14, 256>>>(Wk);

    cudaFuncSetAttribute(mxqa_mma_kernel, cudaFuncAttributeMaxDynamicSharedMemorySize, SMEM_BYTES);
    mxqa_mma_kernel<<<B, NT, SMEM_BYTES>>>(x, q, bk, Wq, v, out);
}

// round 15
// speedup vs baseline: 1.0699x; 1.0699x over previous
#include <cuda_runtime.h>
#include <cstdint>
#include <math.h>

#define BB_L 200
#define BB_D 128
#define BB_H 100
#define NT 1024

// paired A layout: row pitch 68 float2 (136 floats)
#define XA_PITCH2 68

// ---- SMEM layout (float indices) ----
#define OFF_XA  0                           // x fp32 pairs [208][136]     -> 28288 f
#define OFF_WK  (208 * 136)                 // packed tf32 B [16*13*32] f2 -> 13312 f
#define OFF_CV  (OFF_WK + 13312)            // (cj, vv) float2 [112]       ->   224 f
#define OFF_QS  (OFF_CV + 224)              // q row                       ->   128 f
#define OFF_SC  (OFF_QS + 128)              // exp(score)*mask, 208
#define OFF_MK  (OFF_SC + 208)              // mask, 208
#define OFF_SCP (OFF_MK + 208)              // partial scores [208][2]     ->   416 f
#define OFF_RED (OFF_SCP + 416)             // 16
#define SMEM_FLOATS (OFF_RED + 16)
#define SMEM_BYTES (SMEM_FLOATS * 4)

// packed Wk: idx = ((ks*13 + nt)*8 + g)*4 + t  (float2 each), 16*13*8*4 = 6656
__device__ float2 g_wkp[6656];

__device__ __forceinline__ uint32_t to_tf32(float f) {
    uint32_t r;
    asm("cvt.rna.tf32.f32 %0, %1;" : "=r"(r) : "f"(f));
    return r;
}
__device__ __forceinline__ float tanh_fast(float x) {
    float y;
    asm("tanh.approx.f32 %0, %1;" : "=f"(y) : "f"(x));
    return y;
}
__device__ __forceinline__ void mma_tf32(float* c,
                                         uint32_t a0, uint32_t a1, uint32_t a2, uint32_t a3,
                                         uint32_t b0, uint32_t b1) {
    asm volatile(
        "mma.sync.aligned.m16n8k8.row.col.f32.tf32.tf32.f32 "
        "{%0,%1,%2,%3}, {%4,%5,%6,%7}, {%8,%9}, {%0,%1,%2,%3};"
        : "+f"(c[0]), "+f"(c[1]), "+f"(c[2]), "+f"(c[3])
        : "r"(a0), "r"(a1), "r"(a2), "r"(a3), "r"(b0), "r"(b1));
}

// ---------------- prep: pack Wk into MMA fragment order (tf32) ----------------
__global__ void pack_wk_kernel(const float* __restrict__ Wk) {
    int i = blockIdx.x * 256 + threadIdx.x;
    if (i >= 6656) return;
    int t = i & 3;
    int g = (i >> 2) & 7;
    int kn = i >> 5;            // ks*13 + nt
    int nt = kn % 13;
    int ks = kn / 13;
    int j = 8 * nt + g;
    int d0 = 8 * ks + t;
    float w0 = (j < BB_H) ? Wk[d0 * BB_H + j] : 0.f;
    float w1 = (j < BB_H) ? Wk[(d0 + 4) * BB_H + j] : 0.f;
    float2 p;
    p.x = __uint_as_float(to_tf32(w0));
    p.y = __uint_as_float(to_tf32(w1));
    g_wkp[i] = p;
}

__global__ void __launch_bounds__(NT, 1)
mxqa_mma_kernel(const float* __restrict__ x, const float* __restrict__ q,
                const float* __restrict__ bk,
                const float* __restrict__ Wq, const float* __restrict__ v,
                float* __restrict__ out)
{
    extern __shared__ float sm[];
    float* xa = sm + OFF_XA;                       // paired fp32 x
    float2* cvv = reinterpret_cast<float2*>(sm + OFF_CV);
    float* qs = sm + OFF_QS;
    float* sc = sm + OFF_SC;
    float* mk = sm + OFF_MK;
    float* scp = sm + OFF_SCP;
    float* red = sm + OFF_RED;

    const int tid = threadIdx.x;
    const int lane = tid & 31;
    const int warp = tid >> 5;
    const int b = blockIdx.x;
    const int g = lane >> 2;     // fragment row group 0..7
    const int t = lane & 3;      // k/col slot 0..3

    // ---------------- Phase 1a: zero-inits (must complete BEFORE mask writes) ----
    if (tid < 128) qs[tid] = q[(long long)b * 128 + tid];
    if (tid < 208) { sc[tid] = 0.f; mk[tid] = 0.f; }
    // zero ALL 1088 floats of pad rows l = 200..207 (loop: NT=1024 < 1088)
    for (int i = tid; i < 8 * 136; i += NT) xa[200 * 136 + i] = 0.f;
    __syncthreads();   // ORDER: mk/pad zero-init before any staging write (race fix)

    // ---------------- Phase 1b: staging ----------------
    // packed Wk: straight copy (3328 float4)
    {
        const float4* src = reinterpret_cast<const float4*>(g_wkp);
        float4* dst = reinterpret_cast<float4*>(sm + OFF_WK);
        for (int i = tid; i < 3328; i += NT) dst[i] = src[i];
    }

    // x -> paired fp32 SMEM; unit u = (l, ks) covering 8 floats; compute mask
    // (mk[l]=1 writers only after the barrier above: benign same-value race)
    {
        const float4* xb4 = reinterpret_cast<const float4*>(x + (long long)b * (BB_L * BB_D));
        float4* xa4 = reinterpret_cast<float4*>(xa);
        for (int u = tid; u < BB_L * 16; u += NT) {
            int l = u >> 4;
            int ks = u & 15;
            float4 f0 = xb4[2 * u];
            float4 f1 = xb4[2 * u + 1];
            float4 o0, o1;   // pairs (x[8k+t], x[8k+t+4])
            o0.x = f0.x; o0.y = f1.x; o0.z = f0.y; o0.w = f1.y;
            o1.x = f0.z; o1.y = f1.z; o1.z = f0.w; o1.w = f1.w;
            xa4[l * 34 + 2 * ks] = o0;
            xa4[l * 34 + 2 * ks + 1] = o1;
            if (f0.x != 0.f || f0.y != 0.f || f0.z != 0.f || f0.w != 0.f ||
                f1.x != 0.f || f1.y != 0.f || f1.z != 0.f || f1.w != 0.f)
                mk[l] = 1.f;
        }
    }
    __syncthreads();

    // ---------------- Phase 2: GEMM (warps 0-25) || cj (warps 26-31) ----------------
    // warp = 2*mt + half; mt 0..12 owns rows [16mt,16mt+16); half0: nt0-6, half1: nt6-12
    float acc[7][4];
    const int mt = warp >> 1;
    const int half = warp & 1;
    if (warp < 26) {
        const int m0 = mt * 16;
        const float2* pa0 = reinterpret_cast<const float2*>(xa) + (m0 + g) * XA_PITCH2 + t;
        const float2* pa1 = pa0 + 8 * XA_PITCH2;
        // B: uint2 at ((ks*13 + half*6 + nt)*8 + g)*4 + t
        const uint2* pb = reinterpret_cast<const uint2*>(sm + OFF_WK)
                          + (half * 6) * 32 + g * 4 + t;
#pragma unroll
        for (int nt = 0; nt < 7; ++nt)
#pragma unroll
            for (int k = 0; k < 4; ++k) acc[nt][k] = 0.f;

#pragma unroll
        for (int ks = 0; ks < 16; ++ks) {
            float2 p0 = pa0[4 * ks];
            float2 p1 = pa1[4 * ks];
            uint32_t a0 = to_tf32(p0.x);
            uint32_t a1 = to_tf32(p1.x);
            uint32_t a2 = to_tf32(p0.y);
            uint32_t a3 = to_tf32(p1.y);
            const uint2* pbk = pb + ks * 13 * 32;
#pragma unroll
            for (int nt = 0; nt < 7; ++nt) {
                uint2 bb = pbk[nt * 32];
                mma_tf32(acc[nt], a0, a1, a2, a3, bb.x, bb.y);
            }
        }
    } else {
        // cj[j] = bk[j] + sum_d q[d]*Wq[d][j]; vv[j] = v[j] (pad to 104)
        const int j = tid - 26 * 32;   // 0..191, only j<104 active
        if (j < 104) {
            float s = 0.f, vw = 0.f;
            if (j < BB_H) {
                s = bk[j];
#pragma unroll 8
                for (int d = 0; d < 128; ++d) s += qs[d] * Wq[d * BB_H + j];
                vw = v[j];
            }
            cvv[j] = make_float2(s, vw);
        }
    }
    __syncthreads();

    // ---------------- Phase 3: epilogue on fragments (warps 0-25) ----------------
    if (warp < 26) {
        float s0 = 0.f, s1 = 0.f;
#pragma unroll
        for (int nt = 0; nt < 7; ++nt) {
            if (half && nt == 0) continue;          // nt6 duplicate column
            int j0 = half * 48 + nt * 8 + 2 * t;
            float2 c0 = cvv[j0];
            float2 c1 = cvv[j0 + 1];
            s0 += tanh_fast(acc[nt][0] + c0.x) * c0.y;
            s0 += tanh_fast(acc[nt][1] + c1.x) * c1.y;
            s1 += tanh_fast(acc[nt][2] + c0.x) * c0.y;
            s1 += tanh_fast(acc[nt][3] + c1.x) * c1.y;
        }
        s0 += __shfl_xor_sync(0xffffffffu, s0, 1);
        s0 += __shfl_xor_sync(0xffffffffu, s0, 2);
        s1 += __shfl_xor_sync(0xffffffffu, s1, 1);
        s1 += __shfl_xor_sync(0xffffffffu, s1, 2);
        if (t == 0) {
            int l0 = mt * 16 + g;
            scp[2 * l0 + half] = s0;
            scp[2 * (l0 + 8) + half] = s1;
        }
    }
    __syncthreads();

    // ---------------- Phase 4: combine halves, exp, normalize ----------------
    {
        float a = 0.f;
        if (tid < 208) {
            a = expf(scp[2 * tid] + scp[2 * tid + 1]) * mk[tid];
            sc[tid] = a;
        }
        if (warp < 7) {
#pragma unroll
            for (int o = 16; o; o >>= 1) a += __shfl_xor_sync(0xffffffffu, a, o);
            if (lane == 0) red[warp] = a;
        }
    }
    __syncthreads();
    if (tid == 0) {
        float tsum = 0.f;
#pragma unroll
        for (int w = 0; w < 7; ++w) tsum += red[w];
        red[0] = 1.f / (tsum + 1e-7f);
    }
    __syncthreads();
    const float winv = red[0];

    // ---------------- Phase 5: out[b][d] = winv * sum_l sc[l] * x[l][d] (SMEM fp32) ----
    {
        const int d = tid & 127;
        const int oct = tid >> 7;            // 0..7
        // x[l][d] lives at float index l*136 + 8*(d>>3) + 2*((d&7)&3) + ((d&7)>>2)
        const int r = d & 7;
        const int off = 8 * (d >> 3) + 2 * (r & 3) + (r >> 2);
        float a = 0.f;
        const int l0 = oct * 25;
#pragma unroll 5
        for (int l = l0; l < l0 + 25; ++l)
            a += sc[l] * xa[l * 136 + off];
        sm[OFF_WK + tid] = a;                // reuse Wk region (GEMM done, synced)
    }
    __syncthreads();
    if (tid < 128) {
        float o = 0.f;
#pragma unroll
        for (int k = 0; k < 8; ++k) o += sm[OFF_WK + tid + 128 * k];
        out[(long long)b * 128 + tid] = o * winv;
    }
}

extern "C" void kernel_launch(void* const* d_in, const int* in_sizes, int n_in,
                              void* d_out, int out_size)
{
    const float* x  = (const float*)d_in[0];
    const float* q  = (const float*)d_in[1];
    const float* Wk = (const float*)d_in[2];
    const float* bk = (const float*)d_in[3];
    const float* Wq = (const float*)d_in[4];
    const float* v  = (const float*)d_in[5];
    float* out = (float*)d_out;

    const int B = in_sizes[1] / BB_D;  // q is [B, 128]

    pack_wk_kernel<<<26, 256>>>(Wk);

    cudaFuncSetAttribute(mxqa_mma_kernel, cudaFuncAttributeMaxDynamicSharedMemorySize, SMEM_BYTES);
    mxqa_mma_kernel<<<B, NT, SMEM_BYTES>>>(x, q, bk, Wq, v, out);
}